// round 9
// baseline (speedup 1.0000x reference)
#include <cuda_runtime.h>
#include <cuda_fp16.h>
#include <cstdint>

#define BATCH 8
#define NNODE 2048
#define NEDGE 65536
#define HDIM  128
#define NRAD  6
#define TILE_E 128

typedef unsigned long long u64;

// ---------------- device globals (no allocation) ----------------
__device__ float g_u1[HDIM];
__device__ float g_u2[HDIM];
__device__ float g_c[HDIM];
// W3 A-fragments, fp16, 9 k-tiles: kt 0..7 = lin_w[:,256:384];
// kt 8 = augmented node-term channels [u1h,u1l,u1h,u2h,u2l,u2h,ch,cl,0..0].
// index ((tm*9 + kt)*32 + lane) -> uint4 {a0,a1,a2,a3}
__device__ uint4 g_WA[8 * 9 * 32];

// ---------------- smem byte offsets ----------------
#define OFF_B    0        // r fp16 B-fragments (swizzled): 32768 B
#define OFF_B8   32768    // augmented-tile B words, 16B per edge: 2048 B
#define OFF_RBF  34816    // rbf tile [128][8] f32 (padded): 4096 B
#define SMEM_BYTES 38912

// ---------------- helpers ----------------
__device__ __forceinline__ uint32_t smem_u32(const void* p) {
    uint32_t a;
    asm("{ .reg .u64 t; cvta.to.shared.u64 t, %1; cvt.u32.u64 %0, t; }" : "=r"(a) : "l"(p));
    return a;
}
__device__ __forceinline__ uint4 lds128(uint32_t addr) {
    uint4 v;
    asm volatile("ld.shared.v4.b32 {%0,%1,%2,%3}, [%4];"
                 : "=r"(v.x), "=r"(v.y), "=r"(v.z), "=r"(v.w) : "r"(addr));
    return v;
}
__device__ __forceinline__ uint32_t lds32(uint32_t addr) {
    uint32_t v;
    asm volatile("ld.shared.b32 %0, [%1];" : "=r"(v) : "r"(addr));
    return v;
}
__device__ __forceinline__ void sts64(uint32_t addr, u64 v) {
    asm volatile("st.shared.b64 [%0], %1;" :: "r"(addr), "l"(v) : "memory");
}
__device__ __forceinline__ void sts128(uint32_t addr, uint32_t a, uint32_t b,
                                       uint32_t c, uint32_t d) {
    asm volatile("st.shared.v4.b32 [%0], {%1,%2,%3,%4};"
                 :: "r"(addr), "r"(a), "r"(b), "r"(c), "r"(d) : "memory");
}
// packed f16x2: low half <- lo, high half <- hi
__device__ __forceinline__ uint32_t cvt_f16x2(float lo, float hi) {
    uint32_t d;
    asm("cvt.rn.f16x2.f32 %0, %2, %1;" : "=r"(d) : "f"(lo), "f"(hi));
    return d;
}
__device__ __forceinline__ void mma16816(float* d, uint32_t a0, uint32_t a1,
                                         uint32_t a2, uint32_t a3,
                                         uint32_t b0, uint32_t b1) {
    asm volatile(
        "mma.sync.aligned.m16n8k16.row.col.f32.f16.f16.f32 "
        "{%0,%1,%2,%3}, {%4,%5,%6,%7}, {%8,%9}, {%0,%1,%2,%3};"
        : "+f"(d[0]), "+f"(d[1]), "+f"(d[2]), "+f"(d[3])
        : "r"(a0), "r"(a1), "r"(a2), "r"(a3), "r"(b0), "r"(b1));
}
// silu via single-MUFU tanh: z*sigmoid(z) = 0.5z + 0.5z*tanh(0.5z)
__device__ __forceinline__ float silu_t(float z) {
    float h = 0.5f * z;
    float t;
    asm("tanh.approx.f32 %0, %1;" : "=f"(t) : "f"(h));
    return fmaf(h, t, h);
}

// ---------------------------------------------------------------------------
// pre1: u1 = W1@emb_w, u2 = W2@emb_w, c = (W1+W2)@emb_b + lin_b
// ---------------------------------------------------------------------------
__global__ void precompute_uc(const float* __restrict__ emb_w,
                              const float* __restrict__ emb_b,
                              const float* __restrict__ lin_w,
                              const float* __restrict__ lin_b) {
    __shared__ float red[2][3][4];
    const int tid = threadIdx.x;
    const int bid = blockIdx.x;
    const int half = tid >> 7;
    const int o = bid * 2 + half;
    const int h = tid & 127;
    float w1 = lin_w[o * (3 * HDIM) + h];
    float w2 = lin_w[o * (3 * HDIM) + HDIM + h];
    float u1 = w1 * emb_w[h];
    float u2 = w2 * emb_w[h];
    float cc = (w1 + w2) * emb_b[h];
    #pragma unroll
    for (int s = 16; s > 0; s >>= 1) {
        u1 += __shfl_down_sync(0xffffffff, u1, s);
        u2 += __shfl_down_sync(0xffffffff, u2, s);
        cc += __shfl_down_sync(0xffffffff, cc, s);
    }
    const int w4 = (tid >> 5) & 3;
    if ((tid & 31) == 0) {
        red[half][0][w4] = u1; red[half][1][w4] = u2; red[half][2][w4] = cc;
    }
    __syncthreads();
    if ((tid & 127) == 0) {
        g_u1[o] = red[half][0][0] + red[half][0][1] + red[half][0][2] + red[half][0][3];
        g_u2[o] = red[half][1][0] + red[half][1][1] + red[half][1][2] + red[half][1][3];
        g_c[o]  = red[half][2][0] + red[half][2][1] + red[half][2][2] + red[half][2][3]
                  + lin_b[o];
    }
}

// ---------------------------------------------------------------------------
// pre2: pack all 9 A-fragment k-tiles (runs after pre1; reads g_u1/u2/c).
// grid=9, block=256 -> idx 0..2303 covers (tm 0..7, kt 0..8, lane).
// ---------------------------------------------------------------------------
__global__ void precompute_wpack(const float* __restrict__ lin_w) {
    const int idx = blockIdx.x * 256 + threadIdx.x;
    if (idx >= 8 * 9 * 32) return;
    const int lane = idx & 31;
    const int t    = idx >> 5;       // 0..71
    const int kt   = t % 9;
    const int tm   = t / 9;
    const int o0 = tm * 16 + (lane >> 2);
    const int o1 = o0 + 8;
    const int q  = lane & 3;

    if (kt < 8) {
        const int k0 = kt * 16 + q * 2;
        const float* base = lin_w + 2 * HDIM;
        uint32_t a0 = cvt_f16x2(base[o0 * (3 * HDIM) + k0],     base[o0 * (3 * HDIM) + k0 + 1]);
        uint32_t a1 = cvt_f16x2(base[o1 * (3 * HDIM) + k0],     base[o1 * (3 * HDIM) + k0 + 1]);
        uint32_t a2 = cvt_f16x2(base[o0 * (3 * HDIM) + k0 + 8], base[o0 * (3 * HDIM) + k0 + 9]);
        uint32_t a3 = cvt_f16x2(base[o1 * (3 * HDIM) + k0 + 8], base[o1 * (3 * HDIM) + k0 + 9]);
        g_WA[idx] = make_uint4(a0, a1, a2, a3);
    } else {
        // augmented tile: channels (q*2, q*2+1) per o:
        // q0:(u1h,u1l) q1:(u1h,u2h) q2:(u2l,u2h) q3:(ch,cl); k8..15 = 0
        uint32_t a[2];
        #pragma unroll
        for (int r = 0; r < 2; ++r) {
            const int o = r ? o1 : o0;
            float u1 = g_u1[o], u2 = g_u2[o], cc = g_c[o];
            float u1h = __half2float(__float2half_rn(u1));
            float u2h = __half2float(__float2half_rn(u2));
            float chf = __half2float(__float2half_rn(cc));
            float u1l = u1 - u1h, u2l = u2 - u2h, clf = cc - chf;
            uint32_t w;
            if      (q == 0) w = cvt_f16x2(u1h, u1l);
            else if (q == 1) w = cvt_f16x2(u1h, u2h);
            else if (q == 2) w = cvt_f16x2(u2l, u2h);
            else             w = cvt_f16x2(chf, clf);
            a[r] = w;
        }
        g_WA[idx] = make_uint4(a[0], a[1], 0u, 0u);
    }
}

// ---------------------------------------------------------------------------
// Main fused kernel: 32o x 32e warp tile, 2 e-passes, 3 CTAs/SM.
// B layout identical to R8 (kt-paired, parity-swizzled).
// Node terms folded into MMA via augmented k-tile 8.
// ---------------------------------------------------------------------------
__global__ void __launch_bounds__(256, 3)
edge_mlp_kernel(const float* __restrict__ x,
                const float* __restrict__ rbf,
                const int* __restrict__ iidx,
                const int* __restrict__ jidx,
                const float* __restrict__ rbf_w,
                const float* __restrict__ rbf_b,
                float* __restrict__ out) {
    extern __shared__ char sm[];
    const uint32_t sb = smem_u32(sm);

    const int b    = blockIdx.y;
    const int e0   = blockIdx.x * TILE_E;
    const int tid  = threadIdx.x;
    const int wid  = tid >> 5;
    const int lane = tid & 31;

    float* rbf_s = (float*)(sm + OFF_RBF);   // [128][8] padded

    // ---- stage rbf tile into padded rows [e][8] ----
    {
        const float* src = rbf + ((size_t)b * NEDGE + e0) * NRAD;
        #pragma unroll
        for (int it = 0; it < 3; ++it) {
            int idx = tid + it * 256;        // 0..767
            int e = idx / NRAD, m = idx - e * NRAD;
            rbf_s[e * 8 + m] = src[idx];
        }
    }
    // ---- gather x_i/x_j and build augmented B words directly ----
    // word = {(xih,xih),(xil,xjh),(xjh,xjl),(1,1)} per edge, 16B at OFF_B8+e*16
    if (tid < 128) {
        int e = e0 + tid;
        int ii = iidx[e] & (NNODE - 1);
        int jj = jidx[e] & (NNODE - 1);
        float xi = x[b * NNODE + ii];
        float xj = x[b * NNODE + jj];
        float xih = __half2float(__float2half_rn(xi));
        float xjh = __half2float(__float2half_rn(xj));
        float xil = xi - xih, xjl = xj - xjh;
        uint32_t w0 = cvt_f16x2(xi, xi);          // (xih, xih)
        uint32_t w1 = cvt_f16x2(xil, xj);         // (xil, xjh)
        uint32_t w2 = cvt_f16x2(xj, xjl);         // (xjh, xjl)
        uint32_t w3 = 0x3C003C00u;                // (1, 1)
        sts128(sb + OFF_B8 + (uint32_t)tid * 16, w0, w1, w2, w3);
    }
    __syncthreads();

    // ---- r-phase: lane owns 4 k-channels (kb,kb+1,kb+8,kb+9); 16 edges ----
    {
        const int kt = lane >> 2;        // 0..7
        const int q  = lane & 3;         // 0..3
        const int p  = kt >> 1;          // pair 0..3
        const int ph = kt & 1;
        const uint32_t swz = (uint32_t)((p & 1) << 6);
        const int kb = kt * 16 + q * 2;
        const int ks[4] = { kb, kb + 1, kb + 8, kb + 9 };

        float rw[4][NRAD], rb4[4];
        #pragma unroll
        for (int kk = 0; kk < 4; ++kk) {
            rb4[kk] = __ldg(rbf_b + ks[kk]);
            #pragma unroll
            for (int m = 0; m < NRAD; ++m)
                rw[kk][m] = __ldg(rbf_w + ks[kk] * NRAD + m);
        }

        const int ebase = wid * 16;
        #pragma unroll 2
        for (int t = 0; t < 16; ++t) {
            const int e = ebase + t;
            const float4 r03 = *(const float4*)(rbf_s + e * 8);
            const float2 r45 = *(const float2*)(rbf_s + e * 8 + 4);
            const float rv[NRAD] = { r03.x, r03.y, r03.z, r03.w, r45.x, r45.y };

            float z[4];
            #pragma unroll
            for (int kk = 0; kk < 4; ++kk) {
                z[kk] = rb4[kk];
                #pragma unroll
                for (int m = 0; m < NRAD; ++m)
                    z[kk] = fmaf(rv[m], rw[kk][m], z[kk]);
            }
            uint32_t b01 = cvt_f16x2(silu_t(z[0]), silu_t(z[1]));
            uint32_t b23 = cvt_f16x2(silu_t(z[2]), silu_t(z[3]));

            const uint32_t C2 = (uint32_t)(((e >> 3) * 4 + p));
            const uint32_t w  = (uint32_t)(((e & 7) * 4 + q));
            uint32_t addr = sb + OFF_B + C2 * 512 + ((w * 16) ^ swz) + ph * 8;
            sts64(addr, (u64)b01 | ((u64)b23 << 32));
        }
    }
    __syncthreads();

    // ---- mma + epilogue: warp tile 32(o) x 32(e), two e-passes ----
    const int wm = wid & 3;    // o-group: rows wm*32..+31
    const int wq = wid >> 2;   // e sub-group within pass

    float* outb = out + ((size_t)b * NEDGE + e0) * HDIM;

    #pragma unroll
    for (int pass = 0; pass < 2; ++pass) {
        const int we = pass * 2 + wq;          // 32-edge group 0..3

        float acc[2][4][4];
        #pragma unroll
        for (int i = 0; i < 2; ++i)
            #pragma unroll
            for (int j = 0; j < 4; ++j)
                #pragma unroll
                for (int q = 0; q < 4; ++q) acc[i][j][q] = 0.f;

        #pragma unroll
        for (int p = 0; p < 4; ++p) {
            const int kt0 = 2 * p, kt1 = 2 * p + 1;
            uint4 a0e = __ldg(g_WA + ((wm * 2 + 0) * 9 + kt0) * 32 + lane);
            uint4 a0o = __ldg(g_WA + ((wm * 2 + 0) * 9 + kt1) * 32 + lane);
            uint4 a1e = __ldg(g_WA + ((wm * 2 + 1) * 9 + kt0) * 32 + lane);
            uint4 a1o = __ldg(g_WA + ((wm * 2 + 1) * 9 + kt1) * 32 + lane);
            const uint32_t swz = (uint32_t)((p & 1) << 6);
            #pragma unroll
            for (int j = 0; j < 4; ++j) {
                const uint32_t C2 = (uint32_t)(((we * 4 + j) * 4 + p));
                uint4 v = lds128(sb + OFF_B + C2 * 512 + (((uint32_t)lane * 16) ^ swz));
                mma16816(acc[0][j], a0e.x, a0e.y, a0e.z, a0e.w, v.x, v.y);
                mma16816(acc[0][j], a0o.x, a0o.y, a0o.z, a0o.w, v.z, v.w);
                mma16816(acc[1][j], a1e.x, a1e.y, a1e.z, a1e.w, v.x, v.y);
                mma16816(acc[1][j], a1o.x, a1o.y, a1o.z, a1o.w, v.z, v.w);
            }
        }
        // augmented tile (node terms): b1 = 0, a2/a3 = 0
        {
            uint4 ax0 = __ldg(g_WA + ((wm * 2 + 0) * 9 + 8) * 32 + lane);
            uint4 ax1 = __ldg(g_WA + ((wm * 2 + 1) * 9 + 8) * 32 + lane);
            #pragma unroll
            for (int j = 0; j < 4; ++j) {
                uint32_t b0 = lds32(sb + OFF_B8 +
                    (uint32_t)((((we * 4 + j) * 8 + (lane >> 2)) * 16) + (lane & 3) * 4));
                mma16816(acc[0][j], ax0.x, ax0.y, 0u, 0u, b0, 0u);
                mma16816(acc[1][j], ax1.x, ax1.y, 0u, 0u, b0, 0u);
            }
        }

        // ---- epilogue: silu + store (node terms already in acc) ----
        #pragma unroll
        for (int j = 0; j < 4; ++j) {
            const int eb = we * 32 + j * 8 + (lane & 3) * 2;
            #pragma unroll
            for (int i = 0; i < 2; ++i) {
                const int ob = wm * 32 + i * 16 + (lane >> 2);
                #pragma unroll
                for (int h = 0; h < 2; ++h) {           // o vs o+8
                    const int oo = ob + h * 8;
                    outb[(size_t)eb * HDIM + oo]       = silu_t(acc[i][j][h * 2 + 0]);
                    outb[(size_t)(eb + 1) * HDIM + oo] = silu_t(acc[i][j][h * 2 + 1]);
                }
            }
        }
    }
}

// ---------------------------------------------------------------------------
extern "C" void kernel_launch(void* const* d_in, const int* in_sizes, int n_in,
                              void* d_out, int out_size) {
    const float* x     = (const float*)d_in[0];
    const float* rbf   = (const float*)d_in[1];
    const int*   iidx  = (const int*)d_in[2];   // int32 (JAX x64 disabled)
    const int*   jidx  = (const int*)d_in[3];
    const float* emb_w = (const float*)d_in[4];
    const float* emb_b = (const float*)d_in[5];
    const float* rbf_w = (const float*)d_in[6];
    const float* rbf_b = (const float*)d_in[7];
    const float* lin_w = (const float*)d_in[8];
    const float* lin_b = (const float*)d_in[9];
    float* out = (float*)d_out;

    precompute_uc<<<64, 256>>>(emb_w, emb_b, lin_w, lin_b);
    precompute_wpack<<<9, 256>>>(lin_w);

    cudaFuncSetAttribute(edge_mlp_kernel,
                         cudaFuncAttributeMaxDynamicSharedMemorySize, SMEM_BYTES);
    dim3 grid(NEDGE / TILE_E, BATCH);   // (512, 8)
    edge_mlp_kernel<<<grid, 256, SMEM_BYTES>>>(x, rbf, iidx, jidx, rbf_w, rbf_b, out);
}

// round 10
// speedup vs baseline: 1.1430x; 1.1430x over previous
#include <cuda_runtime.h>
#include <cuda_fp16.h>
#include <cstdint>

#define BATCH 8
#define NNODE 2048
#define NEDGE 65536
#define HDIM  128
#define NRAD  6
#define TILE_E 128

typedef unsigned long long u64;

// ---------------- device globals (no allocation) ----------------
// W3 A-fragments, fp16, 9 k-tiles: kt 0..7 = lin_w[:,256:384] (k=0..127);
// kt 8 = augmented node-term channels (k=128..143):
//   A channels per o: [u1h,u1l, u1h,u2h, u2l,u2h, ch,cl, 0...]
//   B channels per e: [xih,xih, xil,xjh, xjh,xjl, 1,1, 0...]
//   -> contributes xi*u1 + xj*u2 + c (residual ~2^-22).
// index ((tm*9 + kt)*32 + lane) -> uint4 {a0,a1,a2,a3}
__device__ uint4 g_WA[8 * 9 * 32];

// ---------------- smem byte offsets ----------------
#define OFF_B    0        // r fp16 B-fragments (swizzled): 32768 B
#define OFF_B8   32768    // augmented-tile B words, 16B per edge: 2048 B
#define OFF_RBF  34816    // rbf tile [128][8] f32 (padded): 4096 B
#define SMEM_BYTES 38912

// ---------------- helpers ----------------
__device__ __forceinline__ uint32_t smem_u32(const void* p) {
    uint32_t a;
    asm("{ .reg .u64 t; cvta.to.shared.u64 t, %1; cvt.u32.u64 %0, t; }" : "=r"(a) : "l"(p));
    return a;
}
__device__ __forceinline__ uint4 lds128(uint32_t addr) {
    uint4 v;
    asm volatile("ld.shared.v4.b32 {%0,%1,%2,%3}, [%4];"
                 : "=r"(v.x), "=r"(v.y), "=r"(v.z), "=r"(v.w) : "r"(addr));
    return v;
}
__device__ __forceinline__ uint32_t lds32(uint32_t addr) {
    uint32_t v;
    asm volatile("ld.shared.b32 %0, [%1];" : "=r"(v) : "r"(addr));
    return v;
}
__device__ __forceinline__ void sts64(uint32_t addr, u64 v) {
    asm volatile("st.shared.b64 [%0], %1;" :: "r"(addr), "l"(v) : "memory");
}
__device__ __forceinline__ void sts128(uint32_t addr, uint32_t a, uint32_t b,
                                       uint32_t c, uint32_t d) {
    asm volatile("st.shared.v4.b32 [%0], {%1,%2,%3,%4};"
                 :: "r"(addr), "r"(a), "r"(b), "r"(c), "r"(d) : "memory");
}
// packed f16x2: low half <- lo, high half <- hi
__device__ __forceinline__ uint32_t cvt_f16x2(float lo, float hi) {
    uint32_t d;
    asm("cvt.rn.f16x2.f32 %0, %2, %1;" : "=r"(d) : "f"(lo), "f"(hi));
    return d;
}
__device__ __forceinline__ void mma16816(float* d, uint32_t a0, uint32_t a1,
                                         uint32_t a2, uint32_t a3,
                                         uint32_t b0, uint32_t b1) {
    asm volatile(
        "mma.sync.aligned.m16n8k16.row.col.f32.f16.f16.f32 "
        "{%0,%1,%2,%3}, {%4,%5,%6,%7}, {%8,%9}, {%0,%1,%2,%3};"
        : "+f"(d[0]), "+f"(d[1]), "+f"(d[2]), "+f"(d[3])
        : "r"(a0), "r"(a1), "r"(a2), "r"(a3), "r"(b0), "r"(b1));
}
// silu via single-MUFU tanh: z*sigmoid(z) = 0.5z + 0.5z*tanh(0.5z)
__device__ __forceinline__ float silu_t(float z) {
    float h = 0.5f * z;
    float t;
    asm("tanh.approx.f32 %0, %1;" : "=f"(t) : "f"(h));
    return fmaf(h, t, h);
}

// ---------------------------------------------------------------------------
// Single precompute kernel (2 launches/replay keeps ncu -s 5 on edge_mlp).
// Packs all 9 A-fragment k-tiles; aug-tile threads compute u1/u2/c inline.
// grid=64, block=256: idx 0..2303 used.
// ---------------------------------------------------------------------------
__global__ void precompute_all(const float* __restrict__ emb_w,
                               const float* __restrict__ emb_b,
                               const float* __restrict__ lin_w,
                               const float* __restrict__ lin_b) {
    const int idx = blockIdx.x * 256 + threadIdx.x;
    if (idx >= 8 * 9 * 32) return;
    const int lane = idx & 31;
    const int t    = idx >> 5;       // 0..71
    const int kt   = t % 9;
    const int tm   = t / 9;
    const int o0 = tm * 16 + (lane >> 2);
    const int o1 = o0 + 8;
    const int q  = lane & 3;

    if (kt < 8) {
        const int k0 = kt * 16 + q * 2;
        const float* base = lin_w + 2 * HDIM;
        uint32_t a0 = cvt_f16x2(base[o0 * (3 * HDIM) + k0],     base[o0 * (3 * HDIM) + k0 + 1]);
        uint32_t a1 = cvt_f16x2(base[o1 * (3 * HDIM) + k0],     base[o1 * (3 * HDIM) + k0 + 1]);
        uint32_t a2 = cvt_f16x2(base[o0 * (3 * HDIM) + k0 + 8], base[o0 * (3 * HDIM) + k0 + 9]);
        uint32_t a3 = cvt_f16x2(base[o1 * (3 * HDIM) + k0 + 8], base[o1 * (3 * HDIM) + k0 + 9]);
        g_WA[idx] = make_uint4(a0, a1, a2, a3);
    } else {
        // augmented tile: compute u1/u2/c for o0,o1 inline (3x128 dot each)
        uint32_t a[2];
        #pragma unroll
        for (int r = 0; r < 2; ++r) {
            const int o = r ? o1 : o0;
            const float* row = lin_w + o * (3 * HDIM);
            float u1 = 0.f, u2 = 0.f, cc = 0.f;
            #pragma unroll 4
            for (int h = 0; h < HDIM; ++h) {
                float w1 = row[h], w2 = row[HDIM + h];
                u1 = fmaf(w1, emb_w[h], u1);
                u2 = fmaf(w2, emb_w[h], u2);
                cc = fmaf(w1 + w2, emb_b[h], cc);
            }
            cc += lin_b[o];
            float u1h = __half2float(__float2half_rn(u1));
            float u2h = __half2float(__float2half_rn(u2));
            float chf = __half2float(__float2half_rn(cc));
            float u1l = u1 - u1h, u2l = u2 - u2h, clf = cc - chf;
            uint32_t w;
            if      (q == 0) w = cvt_f16x2(u1h, u1l);
            else if (q == 1) w = cvt_f16x2(u1h, u2h);
            else if (q == 2) w = cvt_f16x2(u2l, u2h);
            else             w = cvt_f16x2(chf, clf);
            a[r] = w;
        }
        g_WA[idx] = make_uint4(a[0], a[1], 0u, 0u);
    }
}

// ---------------------------------------------------------------------------
// Main fused kernel (R8 structure): 32o x 64e warp tile, 2 CTAs/SM.
// B layout: kt-paired + parity swizzle (2-phase STS, LDS.128 feeds 2 MMAs).
// Node terms folded into MMA via augmented k-tile 8; epilogue = silu + store.
// ---------------------------------------------------------------------------
__global__ void __launch_bounds__(256, 2)
edge_mlp_kernel(const float* __restrict__ x,
                const float* __restrict__ rbf,
                const int* __restrict__ iidx,
                const int* __restrict__ jidx,
                const float* __restrict__ rbf_w,
                const float* __restrict__ rbf_b,
                float* __restrict__ out) {
    extern __shared__ char sm[];
    const uint32_t sb = smem_u32(sm);

    const int b    = blockIdx.y;
    const int e0   = blockIdx.x * TILE_E;
    const int tid  = threadIdx.x;
    const int wid  = tid >> 5;
    const int lane = tid & 31;

    float* rbf_s = (float*)(sm + OFF_RBF);   // [128][8] padded

    // ---- stage rbf tile into padded rows [e][8] ----
    {
        const float* src = rbf + ((size_t)b * NEDGE + e0) * NRAD;
        #pragma unroll
        for (int it = 0; it < 3; ++it) {
            int idx = tid + it * 256;        // 0..767
            int e = idx / NRAD, m = idx - e * NRAD;
            rbf_s[e * 8 + m] = src[idx];
        }
    }
    // ---- gather x_i/x_j, build augmented B words (16B/edge) ----
    // word = {(xih,xih),(xil,xjh),(xjh,xjl),(1,1)}
    if (tid < 128) {
        int e = e0 + tid;
        int ii = iidx[e] & (NNODE - 1);
        int jj = jidx[e] & (NNODE - 1);
        float xi = x[b * NNODE + ii];
        float xj = x[b * NNODE + jj];
        float xih = __half2float(__float2half_rn(xi));
        float xjh = __half2float(__float2half_rn(xj));
        float xil = xi - xih, xjl = xj - xjh;
        uint32_t w0 = cvt_f16x2(xi, xi);
        uint32_t w1 = cvt_f16x2(xil, xj);
        uint32_t w2 = cvt_f16x2(xj, xjl);
        uint32_t w3 = 0x3C003C00u;           // (1, 1)
        sts128(sb + OFF_B8 + (uint32_t)tid * 16, w0, w1, w2, w3);
    }
    __syncthreads();

    // ---- r-phase: lane owns 4 k-channels (kb,kb+1,kb+8,kb+9); 16 edges ----
    {
        const int kt = lane >> 2;        // 0..7
        const int q  = lane & 3;         // 0..3
        const int p  = kt >> 1;          // pair 0..3
        const int ph = kt & 1;
        const uint32_t swz = (uint32_t)((p & 1) << 6);
        const int kb = kt * 16 + q * 2;
        const int ks[4] = { kb, kb + 1, kb + 8, kb + 9 };

        float rw[4][NRAD], rb4[4];
        #pragma unroll
        for (int kk = 0; kk < 4; ++kk) {
            rb4[kk] = __ldg(rbf_b + ks[kk]);
            #pragma unroll
            for (int m = 0; m < NRAD; ++m)
                rw[kk][m] = __ldg(rbf_w + ks[kk] * NRAD + m);
        }

        const int ebase = wid * 16;
        #pragma unroll 2
        for (int t = 0; t < 16; ++t) {
            const int e = ebase + t;
            const float4 r03 = *(const float4*)(rbf_s + e * 8);
            const float2 r45 = *(const float2*)(rbf_s + e * 8 + 4);
            const float rv[NRAD] = { r03.x, r03.y, r03.z, r03.w, r45.x, r45.y };

            float z[4];
            #pragma unroll
            for (int kk = 0; kk < 4; ++kk) {
                z[kk] = rb4[kk];
                #pragma unroll
                for (int m = 0; m < NRAD; ++m)
                    z[kk] = fmaf(rv[m], rw[kk][m], z[kk]);
            }
            uint32_t b01 = cvt_f16x2(silu_t(z[0]), silu_t(z[1]));
            uint32_t b23 = cvt_f16x2(silu_t(z[2]), silu_t(z[3]));

            const uint32_t C2 = (uint32_t)(((e >> 3) * 4 + p));
            const uint32_t w  = (uint32_t)(((e & 7) * 4 + q));
            uint32_t addr = sb + OFF_B + C2 * 512 + ((w * 16) ^ swz) + ph * 8;
            sts64(addr, (u64)b01 | ((u64)b23 << 32));
        }
    }
    __syncthreads();

    // ---- mma: warp tile 32(o) x 64(e); LDS.128 feeds two MMAs ----
    const int wm  = wid & 3;    // o-group: rows wm*32..+31
    const int wng = wid >> 2;   // e-group: cols wng*64..+63

    float acc[2][8][4];
    #pragma unroll
    for (int i = 0; i < 2; ++i)
        #pragma unroll
        for (int j = 0; j < 8; ++j)
            #pragma unroll
            for (int q = 0; q < 4; ++q) acc[i][j][q] = 0.f;

    #pragma unroll
    for (int p = 0; p < 4; ++p) {
        const int kt0 = 2 * p, kt1 = 2 * p + 1;
        uint4 a0e = __ldg(g_WA + ((wm * 2 + 0) * 9 + kt0) * 32 + lane);
        uint4 a0o = __ldg(g_WA + ((wm * 2 + 0) * 9 + kt1) * 32 + lane);
        uint4 a1e = __ldg(g_WA + ((wm * 2 + 1) * 9 + kt0) * 32 + lane);
        uint4 a1o = __ldg(g_WA + ((wm * 2 + 1) * 9 + kt1) * 32 + lane);
        const uint32_t swz = (uint32_t)((p & 1) << 6);
        #pragma unroll
        for (int j = 0; j < 8; ++j) {
            const uint32_t C2 = (uint32_t)(((wng * 8 + j) * 4 + p));
            uint4 v = lds128(sb + OFF_B + C2 * 512 + (((uint32_t)lane * 16) ^ swz));
            mma16816(acc[0][j], a0e.x, a0e.y, a0e.z, a0e.w, v.x, v.y);
            mma16816(acc[0][j], a0o.x, a0o.y, a0o.z, a0o.w, v.z, v.w);
            mma16816(acc[1][j], a1e.x, a1e.y, a1e.z, a1e.w, v.x, v.y);
            mma16816(acc[1][j], a1o.x, a1o.y, a1o.z, a1o.w, v.z, v.w);
        }
    }
    // ---- augmented tile (node terms): a2/a3 = 0, b1 = 0 ----
    {
        uint4 ax0 = __ldg(g_WA + ((wm * 2 + 0) * 9 + 8) * 32 + lane);
        uint4 ax1 = __ldg(g_WA + ((wm * 2 + 1) * 9 + 8) * 32 + lane);
        #pragma unroll
        for (int j = 0; j < 8; ++j) {
            uint32_t b0 = lds32(sb + OFF_B8 +
                (uint32_t)((((wng * 8 + j) * 8 + (lane >> 2)) * 16) + (lane & 3) * 4));
            mma16816(acc[0][j], ax0.x, ax0.y, 0u, 0u, b0, 0u);
            mma16816(acc[1][j], ax1.x, ax1.y, 0u, 0u, b0, 0u);
        }
    }

    // ---- epilogue: silu + store only (node terms already in acc) ----
    float* outb = out + ((size_t)b * NEDGE + e0) * HDIM;
    #pragma unroll
    for (int j = 0; j < 8; ++j) {
        const int eb = wng * 64 + j * 8 + (lane & 3) * 2;
        #pragma unroll
        for (int i = 0; i < 2; ++i) {
            const int ob = wm * 32 + i * 16 + (lane >> 2);
            #pragma unroll
            for (int h = 0; h < 2; ++h) {           // o vs o+8
                const int oo = ob + h * 8;
                outb[(size_t)eb * HDIM + oo]       = silu_t(acc[i][j][h * 2 + 0]);
                outb[(size_t)(eb + 1) * HDIM + oo] = silu_t(acc[i][j][h * 2 + 1]);
            }
        }
    }
}

// ---------------------------------------------------------------------------
extern "C" void kernel_launch(void* const* d_in, const int* in_sizes, int n_in,
                              void* d_out, int out_size) {
    const float* x     = (const float*)d_in[0];
    const float* rbf   = (const float*)d_in[1];
    const int*   iidx  = (const int*)d_in[2];   // int32 (JAX x64 disabled)
    const int*   jidx  = (const int*)d_in[3];
    const float* emb_w = (const float*)d_in[4];
    const float* emb_b = (const float*)d_in[5];
    const float* rbf_w = (const float*)d_in[6];
    const float* rbf_b = (const float*)d_in[7];
    const float* lin_w = (const float*)d_in[8];
    const float* lin_b = (const float*)d_in[9];
    float* out = (float*)d_out;

    precompute_all<<<64, 256>>>(emb_w, emb_b, lin_w, lin_b);

    cudaFuncSetAttribute(edge_mlp_kernel,
                         cudaFuncAttributeMaxDynamicSharedMemorySize, SMEM_BYTES);
    dim3 grid(NEDGE / TILE_E, BATCH);   // (512, 8)
    edge_mlp_kernel<<<grid, 256, SMEM_BYTES>>>(x, rbf, iidx, jidx, rbf_w, rbf_b, out);
}